// round 8
// baseline (speedup 1.0000x reference)
#include <cuda_runtime.h>
#include <cstdint>

// ROI Align, NCHW.  input (4,256,200,200) f32, rois (1024,5), out (1024,256,7,7).
// R8: one CTA per roi; 16 stages x 16 channels, double-buffered cp.async
// pipeline (depth 2). Params computed once per CTA, bin params register-resident.

#define OHW 49
static constexpr int C_  = 256;
static constexpr int H_  = 200;
static constexpr int W_  = 200;
static constexpr int HW_ = H_ * W_;
static constexpr int SC  = 16;             // channels per stage
static constexpr int NS  = C_ / SC;        // 16 stages
static constexpr int P_  = 20;             // row pitch (floats) = 5 quads
static constexpr int CSTR = 16 * P_ + 4;   // 324 floats per channel plane
static constexpr int BUFSZ = SC * CSTR;    // 5184 floats per buffer

__device__ __forceinline__ void cp_async16(uint32_t s_dst, const void* g_src) {
    asm volatile("cp.async.cg.shared.global [%0], [%1], 16;" :: "r"(s_dst), "l"(g_src));
}
__device__ __forceinline__ void cp_commit() {
    asm volatile("cp.async.commit_group;" ::: "memory");
}
template <int N> __device__ __forceinline__ void cp_wait() {
    asm volatile("cp.async.wait_group %0;" :: "n"(N) : "memory");
}

__global__ __launch_bounds__(256) void roi_align_kernel(
    const float* __restrict__ inp,
    const float* __restrict__ rois,
    float* __restrict__ out)
{
    __shared__ float tile[2][BUFSZ];        // 41472 B
    __shared__ float s_lx[7], s_ly[7];
    __shared__ int   s_xr[7], s_yo[7];

    const int m   = blockIdx.x;
    const int tid = threadIdx.x;

    // ---- per-roi scalars (once per CTA; 1024 CTAs total -> negligible) ----
    const float* r = rois + (size_t)m * 5;
    const int   b  = (int)r[0];
    const float x1 = r[1] * 0.25f, y1 = r[2] * 0.25f;
    const float bw = fmaxf(r[3] * 0.25f - x1, 1.0f) * (1.0f / 7.0f);
    const float bh = fmaxf(r[4] * 0.25f - y1, 1.0f) * (1.0f / 7.0f);

    const float px0 = ((x1 + 0.5f * bw) * 199.0f) / 200.0f;
    const float px6 = ((x1 + 6.5f * bw) * 199.0f) / 200.0f;
    const float py0 = ((y1 + 0.5f * bh) * 199.0f) / 200.0f;
    const float py6 = ((y1 + 6.5f * bh) * 199.0f) / 200.0f;
    int xlo = max(0, min((int)floorf(px0), W_ - 1));
    int ylo = max(0, min((int)floorf(py0), H_ - 1));
    int xhi = max(xlo, min((int)floorf(px6) + 1, W_ - 1));
    int yhi = max(ylo, min((int)floorf(py6) + 1, H_ - 1));
    const int ww = min(xhi - xlo + 1, 16);
    const int wh = min(yhi - ylo + 1, 16);
    const int ax = min(xlo & ~3, W_ - P_);
    const int nq = min(5, (xlo - ax + ww + 3) >> 2);

    // ---- bin params (threads 0..13) ----
    if (tid < 7) {
        const float px = ((x1 + ((float)tid + 0.5f) * bw) * 199.0f) / 200.0f;
        const int   x0 = (int)floorf(px);
        s_lx[tid] = px - (float)x0;
        s_xr[tid] = max(0, min(x0 - ax, P_ - 2));
    } else if (tid < 14) {
        const int   t  = tid - 7;
        const float py = ((y1 + ((float)t + 0.5f) * bh) * 199.0f) / 200.0f;
        const int   y0 = (int)floorf(py);
        s_ly[t] = py - (float)y0;
        s_yo[t] = max(0, min(y0 - ylo, 14)) * P_;
    }

    // ---- staging lane map: warp handles channels wid, wid+8 within a stage ----
    const int wid  = tid >> 5;
    const int lane = tid & 31;
    const int rrow = lane / 5;               // 0..6 (lanes 30,31 idle)
    const int rq   = lane - rrow * 5;        // 0..4
    const bool act = (lane < 30) && (rq < nq);
    const float* gbase = inp + (size_t)b * (C_ * HW_) + (size_t)ylo * W_ + ax;

    auto stage = [&](int s) {
        const float* gs = gbase + (size_t)(s * SC) * HW_;
        float* tb = tile[s & 1];
        if (act) {
            #pragma unroll
            for (int cc = 0; cc < 2; cc++) {
                const int c = wid + cc * 8;
                const float* gp = gs + c * HW_;
                uint32_t sp = (uint32_t)__cvta_generic_to_shared(tb + c * CSTR);
                for (int y = rrow; y < wh; y += 6)
                    cp_async16(sp + (uint32_t)(y * P_ + rq * 4) * 4u, gp + y * W_ + rq * 4);
            }
        }
        cp_commit();
    };

    stage(0);
    stage(1);
    __syncthreads();                          // bin params visible

    // ---- register-resident per-thread bin params ----
    const bool comp  = tid < 5 * OHW;         // 245 compute threads
    int cstart = 0, xr = 0, yo = 0;
    float w00 = 0, w01 = 0, w10 = 0, w11 = 0;
    float* op = out;
    if (comp) {
        cstart = tid / OHW;                   // 0..4
        const int bin = tid - cstart * OHW;
        const int ph  = bin / 7;
        const int pw  = bin - ph * 7;
        const float lx = s_lx[pw], ly = s_ly[ph];
        const float hx = 1.0f - lx, hy = 1.0f - ly;
        w00 = hy * hx; w01 = hy * lx; w10 = ly * hx; w11 = ly * lx;
        xr = s_xr[pw]; yo = s_yo[ph];
        op = out + ((size_t)m * C_ + cstart) * OHW + bin;
    }

    #pragma unroll 1
    for (int s = 0; s < NS; s++) {
        if (s < NS - 1) cp_wait<1>(); else cp_wait<0>();
        __syncthreads();                      // buffer s ready for everyone
        if (comp) {
            const float* tp = tile[s & 1] + cstart * CSTR + yo + xr;
            float* o = op + (size_t)s * (SC * OHW);
            #pragma unroll
            for (int c = cstart; c < SC; c += 5, tp += 5 * CSTR, o += 5 * OHW) {
                const float v = w00 * tp[0] + w01 * tp[1]
                              + w10 * tp[P_] + w11 * tp[P_ + 1];
                __stcs(o, v);
            }
        }
        __syncthreads();                      // compute(s) done before reuse
        if (s + 2 < NS) stage(s + 2);
    }
}

extern "C" void kernel_launch(void* const* d_in, const int* in_sizes, int n_in,
                              void* d_out, int out_size)
{
    const float* inp  = (const float*)d_in[0];
    const float* rois = (const float*)d_in[1];
    float*       out  = (float*)d_out;
    const int M = in_sizes[1] / 5;            // 1024
    roi_align_kernel<<<M, 256>>>(inp, rois, out);
}

// round 11
// speedup vs baseline: 1.2766x; 1.2766x over previous
#include <cuda_runtime.h>
#include <cstdint>

// ROI Align, NCHW.  input (4,256,200,200) f32, rois (1024,5), out (1024,256,7,7).
// R11: proven R6 cp.async math, restructured for latency overlap:
//  - CB=16 channels/CTA, 128 threads -> 20.8KB smem -> 10 CTAs/SM (was 5)
//  - two commit groups (8+8 channels); compute half0 overlaps half1's drain
//  - bin params register-resident; 4 LDS + 3 FMA + 1 STG per output

#define OHW 49
static constexpr int C_  = 256;
static constexpr int H_  = 200;
static constexpr int W_  = 200;
static constexpr int HW_ = H_ * W_;
static constexpr int CB  = 16;             // channels per CTA
static constexpr int P_  = 20;             // smem row pitch (floats) = 5 quads
static constexpr int CSTR = 16 * P_ + 4;   // 324 floats per channel plane
static constexpr int NT  = 128;

__device__ __forceinline__ void cp_async16(uint32_t s_dst, const void* g_src) {
    asm volatile("cp.async.cg.shared.global [%0], [%1], 16;" :: "r"(s_dst), "l"(g_src));
}

__global__ __launch_bounds__(NT) void roi_align_kernel(
    const float* __restrict__ inp,
    const float* __restrict__ rois,
    float* __restrict__ out)
{
    __shared__ __align__(16) float tile[CB * CSTR];    // 20736 B
    __shared__ float s_lx[7], s_ly[7];
    __shared__ int   s_xr[7], s_yo[7];

    const int m   = blockIdx.x;
    const int c0  = blockIdx.y * CB;
    const int tid = threadIdx.x;

    // ---- per-roi scalars (identical math to R6, proven) ----
    const float* r = rois + (size_t)m * 5;
    const int   b  = (int)r[0];
    const float x1 = r[1] * 0.25f, y1 = r[2] * 0.25f;
    const float bw = fmaxf(r[3] * 0.25f - x1, 1.0f) * (1.0f / 7.0f);
    const float bh = fmaxf(r[4] * 0.25f - y1, 1.0f) * (1.0f / 7.0f);

    const float px0 = ((x1 + 0.5f * bw) * 199.0f) / 200.0f;
    const float px6 = ((x1 + 6.5f * bw) * 199.0f) / 200.0f;
    const float py0 = ((y1 + 0.5f * bh) * 199.0f) / 200.0f;
    const float py6 = ((y1 + 6.5f * bh) * 199.0f) / 200.0f;
    int xlo = max(0, min((int)floorf(px0), W_ - 1));
    int ylo = max(0, min((int)floorf(py0), H_ - 1));
    int xhi = max(xlo, min((int)floorf(px6) + 1, W_ - 1));
    int yhi = max(ylo, min((int)floorf(py6) + 1, H_ - 1));
    const int ww = min(xhi - xlo + 1, 16);
    const int wh = min(yhi - ylo + 1, 16);
    const int ax = min(xlo & ~3, W_ - P_);
    const int nq = min(5, (xlo - ax + ww + 3) >> 2);

    // ---- per-bin params (threads 0..13) ----
    if (tid < 7) {
        const float px = ((x1 + ((float)tid + 0.5f) * bw) * 199.0f) / 200.0f;
        const int   x0 = (int)floorf(px);
        s_lx[tid] = px - (float)x0;
        s_xr[tid] = max(0, min(x0 - ax, P_ - 2));
    } else if (tid < 14) {
        const int   t  = tid - 7;
        const float py = ((y1 + ((float)t + 0.5f) * bh) * 199.0f) / 200.0f;
        const int   y0 = (int)floorf(py);
        s_ly[t] = py - (float)y0;
        s_yo[t] = max(0, min(y0 - ylo, 14)) * P_;
    }

    // ---- stage two commit groups of 8 channels each ----
    const int wid  = tid >> 5;               // 0..3
    const int lane = tid & 31;
    const int rrow = lane / 5;               // 0..5 (lanes 30,31 idle)
    const int rq   = lane - rrow * 5;        // 0..4
    const bool act = (lane < 30) && (rq < nq);
    const float* base = inp + ((size_t)b * C_ + c0) * (size_t)HW_
                            + (size_t)ylo * W_ + ax;

    #pragma unroll
    for (int g = 0; g < 2; g++) {
        if (act) {
            #pragma unroll
            for (int cc = 0; cc < 2; cc++) {
                const int c = g * 8 + wid + cc * 4;
                const float* gp = base + (size_t)c * HW_;
                uint32_t sp = (uint32_t)__cvta_generic_to_shared(tile + c * CSTR);
                for (int y = rrow; y < wh; y += 6)
                    cp_async16(sp + (uint32_t)(y * P_ + rq * 4) * 4u,
                               gp + y * W_ + rq * 4);
            }
        }
        asm volatile("cp.async.commit_group;" ::: "memory");
    }

    // ---- wait group0, then compute half 0 while half 1 drains ----
    asm volatile("cp.async.wait_group 1;" ::: "memory");
    __syncthreads();                         // bin params + group0 visible

    const bool comp = tid < 2 * OHW;         // 98 compute threads
    int cstart = 0, xr = 0, yo = 0;
    float w00 = 0, w01 = 0, w10 = 0, w11 = 0;
    if (comp) {
        cstart = (tid >= OHW) ? 1 : 0;
        const int bin = tid - cstart * OHW;
        const int ph  = bin / 7;
        const int pw  = bin - ph * 7;
        const float lx = s_lx[pw], ly = s_ly[ph];
        const int   xri = s_xr[pw], yoi = s_yo[ph];
        const float hx = 1.0f - lx, hy = 1.0f - ly;
        w00 = hy * hx; w01 = hy * lx; w10 = ly * hx; w11 = ly * lx;
        xr = xri; yo = yoi;

        const float* tp = tile + cstart * CSTR + yo + xr;
        float* op = out + ((size_t)m * C_ + c0 + cstart) * OHW + bin;
        #pragma unroll
        for (int k = 0; k < 4; k++, tp += 2 * CSTR, op += 2 * OHW) {
            const float v = w00 * tp[0] + w01 * tp[1]
                          + w10 * tp[P_] + w11 * tp[P_ + 1];
            __stcs(op, v);
        }
    }

    // ---- wait group1, compute half 1 ----
    asm volatile("cp.async.wait_group 0;" ::: "memory");
    __syncthreads();
    if (comp) {
        const int bin = tid - cstart * OHW;
        const float* tp = tile + (8 + cstart) * CSTR + yo + xr;
        float* op = out + ((size_t)m * C_ + c0 + 8 + cstart) * OHW + bin;
        #pragma unroll
        for (int k = 0; k < 4; k++, tp += 2 * CSTR, op += 2 * OHW) {
            const float v = w00 * tp[0] + w01 * tp[1]
                          + w10 * tp[P_] + w11 * tp[P_ + 1];
            __stcs(op, v);
        }
    }
}

extern "C" void kernel_launch(void* const* d_in, const int* in_sizes, int n_in,
                              void* d_out, int out_size)
{
    const float* inp  = (const float*)d_in[0];
    const float* rois = (const float*)d_in[1];
    float*       out  = (float*)d_out;
    const int M = in_sizes[1] / 5;           // 1024
    dim3 grid(M, C_ / CB);                   // (1024, 16)
    roi_align_kernel<<<grid, NT>>>(inp, rois, out);
}

// round 12
// speedup vs baseline: 1.3393x; 1.0491x over previous
#include <cuda_runtime.h>
#include <cstdint>

// ROI Align, NCHW.  input (4,256,200,200) f32, rois (1024,5), out (1024,256,7,7).
// R12: amortize per-CTA overhead. CTA = (roi, 32-channel block) as 4 pipelined
// groups of 8 channels, double-buffered (smem 20.7KB -> 10 CTAs/SM kept).
// Prologue/lane-map/bin-setup run once per 32 channels (was per 16).
// Staging y-loop fully unrolled (3 predicated cp.asyncs).

#define OHW 49
static constexpr int C_   = 256;
static constexpr int H_   = 200;
static constexpr int W_   = 200;
static constexpr int HW_  = H_ * W_;
static constexpr int GC   = 8;              // channels per group
static constexpr int NG   = 4;              // groups per CTA (32 channels)
static constexpr int P_   = 20;             // smem row pitch (floats) = 5 quads
static constexpr int CSTR = 16 * P_ + 4;    // 324 floats per channel plane
static constexpr int BUF  = GC * CSTR;      // 2592 floats per buffer
static constexpr int NT   = 128;

__device__ __forceinline__ void cp_async16(uint32_t s_dst, const void* g_src) {
    asm volatile("cp.async.cg.shared.global [%0], [%1], 16;" :: "r"(s_dst), "l"(g_src));
}
__device__ __forceinline__ void cp_commit() {
    asm volatile("cp.async.commit_group;" ::: "memory");
}

__global__ __launch_bounds__(NT) void roi_align_kernel(
    const float* __restrict__ inp,
    const float* __restrict__ rois,
    float* __restrict__ out)
{
    __shared__ __align__(16) float tile[2][BUF];       // 20736 B
    __shared__ float s_lx[7], s_ly[7];
    __shared__ int   s_xr[7], s_yo[7];

    const int m   = blockIdx.x;
    const int c0  = blockIdx.y * (GC * NG);
    const int tid = threadIdx.x;

    // ---- per-roi scalars (proven R6 math; once per 32 channels now) ----
    const float* r = rois + (size_t)m * 5;
    const int   b  = (int)r[0];
    const float x1 = r[1] * 0.25f, y1 = r[2] * 0.25f;
    const float bw = fmaxf(r[3] * 0.25f - x1, 1.0f) * (1.0f / 7.0f);
    const float bh = fmaxf(r[4] * 0.25f - y1, 1.0f) * (1.0f / 7.0f);

    const float px0 = ((x1 + 0.5f * bw) * 199.0f) / 200.0f;
    const float px6 = ((x1 + 6.5f * bw) * 199.0f) / 200.0f;
    const float py0 = ((y1 + 0.5f * bh) * 199.0f) / 200.0f;
    const float py6 = ((y1 + 6.5f * bh) * 199.0f) / 200.0f;
    int xlo = max(0, min((int)floorf(px0), W_ - 1));
    int ylo = max(0, min((int)floorf(py0), H_ - 1));
    int xhi = max(xlo, min((int)floorf(px6) + 1, W_ - 1));
    int yhi = max(ylo, min((int)floorf(py6) + 1, H_ - 1));
    const int ww = min(xhi - xlo + 1, 16);
    const int wh = min(yhi - ylo + 1, 16);
    const int ax = min(xlo & ~3, W_ - P_);
    const int nq = min(5, (xlo - ax + ww + 3) >> 2);

    // ---- per-bin params (threads 0..13) ----
    if (tid < 7) {
        const float px = ((x1 + ((float)tid + 0.5f) * bw) * 199.0f) / 200.0f;
        const int   x0 = (int)floorf(px);
        s_lx[tid] = px - (float)x0;
        s_xr[tid] = max(0, min(x0 - ax, P_ - 2));
    } else if (tid < 14) {
        const int   t  = tid - 7;
        const float py = ((y1 + ((float)t + 0.5f) * bh) * 199.0f) / 200.0f;
        const int   y0 = (int)floorf(py);
        s_ly[t] = py - (float)y0;
        s_yo[t] = max(0, min(y0 - ylo, 14)) * P_;
    }

    // ---- staging lane map (once) ----
    const int wid  = tid >> 5;               // 0..3
    const int lane = tid & 31;
    const int rrow = lane / 5;               // 0..5 (lanes 30,31 idle)
    const int rq   = lane - rrow * 5;        // 0..4
    const bool act = (lane < 30) && (rq < nq);
    const float* base = inp + ((size_t)b * C_ + c0) * (size_t)HW_
                            + (size_t)ylo * W_ + ax;
    const bool p0 = act && (rrow      < wh);
    const bool p1 = act && (rrow + 6  < wh);
    const bool p2 = act && (rrow + 12 < wh);
    const uint32_t so0 = (uint32_t)((rrow      ) * P_ + rq * 4) * 4u;
    const uint32_t so1 = so0 + 6u * P_ * 4u;
    const uint32_t so2 = so1 + 6u * P_ * 4u;
    const int go0 = (rrow      ) * W_ + rq * 4;
    const int go1 = go0 + 6 * W_;
    const int go2 = go1 + 6 * W_;

    auto stage = [&](int g, int buf) {
        #pragma unroll
        for (int cc = 0; cc < 2; cc++) {
            const int cl = wid + cc * 4;                 // 0..7 in group
            const float* gp = base + (size_t)(g * GC + cl) * HW_;
            uint32_t sp = (uint32_t)__cvta_generic_to_shared(tile[buf] + cl * CSTR);
            if (p0) cp_async16(sp + so0, gp + go0);
            if (p1) cp_async16(sp + so1, gp + go1);
            if (p2) cp_async16(sp + so2, gp + go2);
        }
        cp_commit();
    };

    stage(0, 0);
    stage(1, 1);

    asm volatile("cp.async.wait_group 1;" ::: "memory");
    __syncthreads();                         // bin params + group0 visible

    // ---- register-resident bin params (once) ----
    const bool comp = tid < 2 * OHW;         // 98 compute threads
    int cstart = 0, xr = 0, yo = 0;
    float w00 = 0, w01 = 0, w10 = 0, w11 = 0;
    size_t obase = 0;
    if (comp) {
        cstart = (tid >= OHW) ? 1 : 0;
        const int bin = tid - cstart * OHW;
        const int ph  = bin / 7;
        const int pw  = bin - ph * 7;
        const float lx = s_lx[pw], ly = s_ly[ph];
        const float hx = 1.0f - lx, hy = 1.0f - ly;
        w00 = hy * hx; w01 = hy * lx; w10 = ly * hx; w11 = ly * lx;
        xr = s_xr[pw]; yo = s_yo[ph];
        obase = ((size_t)m * C_ + c0 + cstart) * OHW + bin;
    }

    auto compute = [&](int g, int buf) {
        if (comp) {
            const float* tp = tile[buf] + cstart * CSTR + yo + xr;
            float* op = out + obase + (size_t)(g * GC) * OHW;
            #pragma unroll
            for (int k = 0; k < 4; k++, tp += 2 * CSTR, op += 2 * OHW) {
                const float v = w00 * tp[0] + w01 * tp[1]
                              + w10 * tp[P_] + w11 * tp[P_ + 1];
                __stcs(op, v);
            }
        }
    };

    // g0 ready now.
    compute(0, 0);
    __syncthreads();                         // buf0 consumed
    stage(2, 0);
    asm volatile("cp.async.wait_group 1;" ::: "memory");   // g1 done (g2 in flight)
    __syncthreads();
    compute(1, 1);
    __syncthreads();                         // buf1 consumed
    stage(3, 1);
    asm volatile("cp.async.wait_group 1;" ::: "memory");   // g2 done (g3 in flight)
    __syncthreads();
    compute(2, 0);
    asm volatile("cp.async.wait_group 0;" ::: "memory");   // g3 done
    __syncthreads();
    compute(3, 1);
}

extern "C" void kernel_launch(void* const* d_in, const int* in_sizes, int n_in,
                              void* d_out, int out_size)
{
    const float* inp  = (const float*)d_in[0];
    const float* rois = (const float*)d_in[1];
    float*       out  = (float*)d_out;
    const int M = in_sizes[1] / 5;           // 1024
    dim3 grid(M, C_ / (GC * NG));            // (1024, 8)
    roi_align_kernel<<<grid, NT>>>(inp, rois, out);
}